// round 14
// baseline (speedup 1.0000x reference)
#include <cuda_runtime.h>
#include <math.h>

#define BB 4
#define NN 2048
#define MM 2048

// ---- persistent scratch (device globals; no allocation allowed) ----
__device__ __align__(16) float g_d2[BB * NN * MM];   // 64 MB squared distances (L2-resident)
__device__ float g_cmin[BB * NN * 16];               // per-row 128-col chunk minima
__device__ float g_remainL[BB * NN];
__device__ __align__(16) float g_R[2][BB * MM];      // remainR double buffer
__device__ float g_ratioL[BB * NN];
__device__ __align__(16) float g_colA[2][BB * MM];   // colsum w0*ratioL, double buffer
__device__ __align__(16) float g_colB[3][BB * MM];   // colsum w, triple buffer (rotation)
__device__ float g_cost[BB];

__device__ __forceinline__ float ex2a(float x) {
    float y; asm("ex2.approx.f32 %0, %1;" : "=f"(y) : "f"(x)); return y;
}
__device__ __forceinline__ float sqrta(float x) {
    float y; asm("sqrt.approx.f32 %0, %1;" : "=f"(y) : "f"(x)); return y;
}

// ---- d2 (literal fp32 rounding) + chunk minima + state init
__global__ void k_d2(const float* __restrict__ tm, const float* __restrict__ sr) {
    __shared__ alignas(16) float sx[MM];
    __shared__ alignas(16) float sy[MM];
    __shared__ alignas(16) float sz[MM];
    int b = blockIdx.y;
    const float* sb = sr + (size_t)b * MM * 3;
    for (int i = threadIdx.x; i < MM; i += blockDim.x) {
        sx[i] = sb[3 * i]; sy[i] = sb[3 * i + 1]; sz[i] = sb[3 * i + 2];
    }
    if (blockIdx.x == 0) {       // one block per batch initializes state
        int bo = b * MM;
        for (int i = threadIdx.x; i < MM; i += blockDim.x) {
            g_remainL[b * NN + i] = 1.0f;   // multiL = 1 (N == M)
            g_R[0][bo + i] = 1.0f;
            g_R[1][bo + i] = 1.0f;
            g_colA[0][bo + i] = 0.0f;
            g_colA[1][bo + i] = 0.0f;
            g_colB[0][bo + i] = 0.0f;
            g_colB[1][bo + i] = 0.0f;
            g_colB[2][bo + i] = 0.0f;
        }
        if (threadIdx.x == 0) g_cost[b] = 0.0f;
    }
    __syncthreads();
    int warp = threadIdx.x >> 5, lane = threadIdx.x & 31;
    int n = blockIdx.x * 8 + warp;
    size_t row = (size_t)(b * NN + n);
    const float* tp = tm + row * 3;
    float tx = tp[0], ty = tp[1], tz = tp[2];
    float* drow = g_d2 + row * MM;
#pragma unroll 2
    for (int it = 0; it < 16; ++it) {
        int m = it * 128 + lane * 4;
        float4 X = *(const float4*)(sx + m);
        float4 Y = *(const float4*)(sy + m);
        float4 Z = *(const float4*)(sz + m);
        float4 o;
        { float dx = __fadd_rn(tx, -X.x), dy = __fadd_rn(ty, -Y.x), dz = __fadd_rn(tz, -Z.x);
          o.x = __fadd_rn(__fadd_rn(__fmul_rn(dx, dx), __fmul_rn(dy, dy)), __fmul_rn(dz, dz)); }
        { float dx = __fadd_rn(tx, -X.y), dy = __fadd_rn(ty, -Y.y), dz = __fadd_rn(tz, -Z.y);
          o.y = __fadd_rn(__fadd_rn(__fmul_rn(dx, dx), __fmul_rn(dy, dy)), __fmul_rn(dz, dz)); }
        { float dx = __fadd_rn(tx, -X.z), dy = __fadd_rn(ty, -Y.z), dz = __fadd_rn(tz, -Z.z);
          o.z = __fadd_rn(__fadd_rn(__fmul_rn(dx, dx), __fmul_rn(dy, dy)), __fmul_rn(dz, dz)); }
        { float dx = __fadd_rn(tx, -X.w), dy = __fadd_rn(ty, -Y.w), dz = __fadd_rn(tz, -Z.w);
          o.w = __fadd_rn(__fadd_rn(__fmul_rn(dx, dx), __fmul_rn(dy, dy)), __fmul_rn(dz, dz)); }
        *(float4*)(drow + m) = o;
        float mn = fminf(fminf(o.x, o.y), fminf(o.z, o.w));
#pragma unroll
        for (int s = 16; s; s >>= 1) mn = fminf(mn, __shfl_xor_sync(0xffffffffu, mn, s));
        if (lane == 0) g_cmin[row * 16 + it] = mn;
    }
}

// --------------------------------------------------------------- kA
// Level j: j2 = j%2, j3 = j%3, j3p = (j+2)%3.
// Phase 1: rm_eff = max(R[j2] - colB[j3p], 0) on the fly; suml -> ratioL.
// Phase 2: colA[j2][c] += sum_rows w0*ratioL; zero colB[j3] (used by kB(j);
//   its previous readers finished at level j-2; rotation makes this safe).
__global__ void __launch_bounds__(256, 5) kA(float kl2, int j2, int j3, int j3p) {
    __shared__ float s_rl[8];
    __shared__ float s_cm[8 * 16];
    int b = blockIdx.y;
    int row0 = blockIdx.x * 8;
    if (threadIdx.x < 128)
        s_cm[threadIdx.x] = g_cmin[(size_t)(b * NN + row0) * 16 + threadIdx.x];
    __syncthreads();
    int warp = threadIdx.x >> 5, lane = threadIdx.x & 31;
    // ---- phase 1: one row per warp
    {
        size_t row = (size_t)(b * NN + row0 + warp);
        const float* drow = g_d2 + row * MM;
        const float* rmg = g_R[j2] + b * MM;
        const float* cbg = g_colB[j3p] + b * MM;
        float suml = 0.0f;
#pragma unroll 2
        for (int it = 0; it < 16; ++it) {
            if (__fmul_rn(kl2, s_cm[warp * 16 + it]) > -126.0f) {
                int m = it * 128 + lane * 4;
                float4 d4 = *(const float4*)(drow + m);
                float4 rm = __ldg((const float4*)(rmg + m));
                float4 cb = __ldg((const float4*)(cbg + m));
                rm.x = fmaxf(__fadd_rn(rm.x, -cb.x), 0.0f);
                rm.y = fmaxf(__fadd_rn(rm.y, -cb.y), 0.0f);
                rm.z = fmaxf(__fadd_rn(rm.z, -cb.z), 0.0f);
                rm.w = fmaxf(__fadd_rn(rm.w, -cb.w), 0.0f);
                suml = fmaf(ex2a(__fmul_rn(kl2, d4.x)), rm.x, suml);
                suml = fmaf(ex2a(__fmul_rn(kl2, d4.y)), rm.y, suml);
                suml = fmaf(ex2a(__fmul_rn(kl2, d4.z)), rm.z, suml);
                suml = fmaf(ex2a(__fmul_rn(kl2, d4.w)), rm.w, suml);
            }
        }
#pragma unroll
        for (int o = 16; o; o >>= 1) suml += __shfl_xor_sync(0xffffffffu, suml, o);
        if (lane == 0) {
            float rl = g_remainL[row] / (suml + 1e-9f);
            s_rl[warp] = rl;
            g_ratioL[row] = rl;
        }
    }
    __syncthreads();
    // ---- phase 2: thread owns cols 4*tid + 1024*k (k = 0,1)
    int c4 = threadIdx.x * 4;
    float4 acc0 = make_float4(0, 0, 0, 0), acc1 = make_float4(0, 0, 0, 0);
    int ch0 = warp, ch1 = warp + 8;
#pragma unroll 2
    for (int r = 0; r < 8; ++r) {
        const float* drow = g_d2 + ((size_t)(b * NN + row0 + r)) * MM;
        float rl = s_rl[r];
        bool a0 = __fmul_rn(kl2, s_cm[r * 16 + ch0]) > -126.0f;
        bool a1 = __fmul_rn(kl2, s_cm[r * 16 + ch1]) > -126.0f;
        float4 d40, d41;
        if (a0) d40 = *(const float4*)(drow + c4);
        if (a1) d41 = *(const float4*)(drow + c4 + 1024);
        if (a0) {
            acc0.x = fmaf(ex2a(__fmul_rn(kl2, d40.x)), rl, acc0.x);
            acc0.y = fmaf(ex2a(__fmul_rn(kl2, d40.y)), rl, acc0.y);
            acc0.z = fmaf(ex2a(__fmul_rn(kl2, d40.z)), rl, acc0.z);
            acc0.w = fmaf(ex2a(__fmul_rn(kl2, d40.w)), rl, acc0.w);
        }
        if (a1) {
            acc1.x = fmaf(ex2a(__fmul_rn(kl2, d41.x)), rl, acc1.x);
            acc1.y = fmaf(ex2a(__fmul_rn(kl2, d41.y)), rl, acc1.y);
            acc1.z = fmaf(ex2a(__fmul_rn(kl2, d41.z)), rl, acc1.z);
            acc1.w = fmaf(ex2a(__fmul_rn(kl2, d41.w)), rl, acc1.w);
        }
    }
    float* colA = g_colA[j2] + b * MM;
    if (acc0.x != 0.0f) atomicAdd(&colA[c4 + 0], acc0.x);
    if (acc0.y != 0.0f) atomicAdd(&colA[c4 + 1], acc0.y);
    if (acc0.z != 0.0f) atomicAdd(&colA[c4 + 2], acc0.z);
    if (acc0.w != 0.0f) atomicAdd(&colA[c4 + 3], acc0.w);
    if (acc1.x != 0.0f) atomicAdd(&colA[c4 + 1024], acc1.x);
    if (acc1.y != 0.0f) atomicAdd(&colA[c4 + 1025], acc1.y);
    if (acc1.z != 0.0f) atomicAdd(&colA[c4 + 1026], acc1.z);
    if (acc1.w != 0.0f) atomicAdd(&colA[c4 + 1027], acc1.w);
    // zero colB[j3] for kB(j)'s accumulation (duplicate zero-writes benign)
    float* cbz = g_colB[j3] + b * MM;
    float4 z4 = make_float4(0.0f, 0.0f, 0.0f, 0.0f);
    *(float4*)(cbz + c4) = z4;
    *(float4*)(cbz + c4 + 1024) = z4;
}

// --------------------------------------------------------------- kB
// Prologue per column thread: rm_eff = max(R[j2]-colB[j3p],0) (bit-identical
// to kA's expression); persist R[1-j2] = rm_eff (duplicate identical writes);
// ratioR = rm_eff/(colA[j2]+1e-9); zero colA[1-j2] for kA(j+1).
// Hot loop: w = (w0*ratioL)*ratioR; colB[j3] += colsum; remainL -= rowsum;
// cost += w*sqrt(max(d2,1e-24)).
__global__ void __launch_bounds__(256, 5) kB(float kl2, int j2, int j3, int j3p) {
    __shared__ float s_rl[8];
    __shared__ float s_rowsum[8];
    __shared__ float s_cost[8];
    __shared__ float s_cm[8 * 16];
    int b = blockIdx.y;
    int row0 = blockIdx.x * 8;
    if (threadIdx.x < 128)
        s_cm[threadIdx.x] = g_cmin[(size_t)(b * NN + row0) * 16 + threadIdx.x];
    if (threadIdx.x < 8) {
        s_rl[threadIdx.x] = g_ratioL[b * NN + row0 + threadIdx.x];
        s_rowsum[threadIdx.x] = 0.0f;
    }
    __syncthreads();
    int warp = threadIdx.x >> 5, lane = threadIdx.x & 31;
    int c4 = threadIdx.x * 4;
    int ch0 = warp, ch1 = warp + 8;
    // ---- prologue: remainR update + ratioR for this thread's 8 columns
    const float* Rrd = g_R[j2] + b * MM;
    float* Rwr = g_R[1 - j2] + b * MM;
    const float* cbp = g_colB[j3p] + b * MM;
    const float* cag = g_colA[j2] + b * MM;
    float* caz = g_colA[1 - j2] + b * MM;
    float4 rm0 = __ldg((const float4*)(Rrd + c4));
    float4 rm1 = __ldg((const float4*)(Rrd + c4 + 1024));
    float4 cb0 = __ldg((const float4*)(cbp + c4));
    float4 cb1 = __ldg((const float4*)(cbp + c4 + 1024));
    float4 ca0 = __ldg((const float4*)(cag + c4));
    float4 ca1 = __ldg((const float4*)(cag + c4 + 1024));
    float4 rme0, rme1;
    rme0.x = fmaxf(__fadd_rn(rm0.x, -cb0.x), 0.0f);
    rme0.y = fmaxf(__fadd_rn(rm0.y, -cb0.y), 0.0f);
    rme0.z = fmaxf(__fadd_rn(rm0.z, -cb0.z), 0.0f);
    rme0.w = fmaxf(__fadd_rn(rm0.w, -cb0.w), 0.0f);
    rme1.x = fmaxf(__fadd_rn(rm1.x, -cb1.x), 0.0f);
    rme1.y = fmaxf(__fadd_rn(rm1.y, -cb1.y), 0.0f);
    rme1.z = fmaxf(__fadd_rn(rm1.z, -cb1.z), 0.0f);
    rme1.w = fmaxf(__fadd_rn(rm1.w, -cb1.w), 0.0f);
    *(float4*)(Rwr + c4) = rme0;             // persist remainR for level j+1
    *(float4*)(Rwr + c4 + 1024) = rme1;
    float4 rr0, rr1;
    rr0.x = rme0.x / (ca0.x + 1e-9f); rr0.y = rme0.y / (ca0.y + 1e-9f);
    rr0.z = rme0.z / (ca0.z + 1e-9f); rr0.w = rme0.w / (ca0.w + 1e-9f);
    rr1.x = rme1.x / (ca1.x + 1e-9f); rr1.y = rme1.y / (ca1.y + 1e-9f);
    rr1.z = rme1.z / (ca1.z + 1e-9f); rr1.w = rme1.w / (ca1.w + 1e-9f);
    float4 z4 = make_float4(0.0f, 0.0f, 0.0f, 0.0f);
    *(float4*)(caz + c4) = z4;               // zero colA[1-j2] for kA(j+1)
    *(float4*)(caz + c4 + 1024) = z4;
    float4 col0 = make_float4(0, 0, 0, 0), col1 = make_float4(0, 0, 0, 0);
    float costw = 0.0f;
#pragma unroll 2
    for (int r = 0; r < 8; ++r) {
        float rl = s_rl[r];
        const float* drow = g_d2 + ((size_t)(b * NN + row0 + r)) * MM;
        bool a0 = (rl != 0.0f) && (__fmul_rn(kl2, s_cm[r * 16 + ch0]) > -126.0f);
        bool a1 = (rl != 0.0f) && (__fmul_rn(kl2, s_cm[r * 16 + ch1]) > -126.0f);
        float4 d40, d41;
        if (a0) d40 = *(const float4*)(drow + c4);
        if (a1) d41 = *(const float4*)(drow + c4 + 1024);
        float rowpart = 0.0f;
        if (a0) {
            float w0 = __fmul_rn(__fmul_rn(ex2a(__fmul_rn(kl2, d40.x)), rl), rr0.x);
            float w1 = __fmul_rn(__fmul_rn(ex2a(__fmul_rn(kl2, d40.y)), rl), rr0.y);
            float w2 = __fmul_rn(__fmul_rn(ex2a(__fmul_rn(kl2, d40.z)), rl), rr0.z);
            float w3 = __fmul_rn(__fmul_rn(ex2a(__fmul_rn(kl2, d40.w)), rl), rr0.w);
            col0.x = __fadd_rn(col0.x, w0); col0.y = __fadd_rn(col0.y, w1);
            col0.z = __fadd_rn(col0.z, w2); col0.w = __fadd_rn(col0.w, w3);
            rowpart = __fadd_rn(rowpart, __fadd_rn(__fadd_rn(w0, w1), __fadd_rn(w2, w3)));
            costw = fmaf(w0, sqrta(fmaxf(d40.x, 1e-24f)), costw);
            costw = fmaf(w1, sqrta(fmaxf(d40.y, 1e-24f)), costw);
            costw = fmaf(w2, sqrta(fmaxf(d40.z, 1e-24f)), costw);
            costw = fmaf(w3, sqrta(fmaxf(d40.w, 1e-24f)), costw);
        }
        if (a1) {
            float w0 = __fmul_rn(__fmul_rn(ex2a(__fmul_rn(kl2, d41.x)), rl), rr1.x);
            float w1 = __fmul_rn(__fmul_rn(ex2a(__fmul_rn(kl2, d41.y)), rl), rr1.y);
            float w2 = __fmul_rn(__fmul_rn(ex2a(__fmul_rn(kl2, d41.z)), rl), rr1.z);
            float w3 = __fmul_rn(__fmul_rn(ex2a(__fmul_rn(kl2, d41.w)), rl), rr1.w);
            col1.x = __fadd_rn(col1.x, w0); col1.y = __fadd_rn(col1.y, w1);
            col1.z = __fadd_rn(col1.z, w2); col1.w = __fadd_rn(col1.w, w3);
            rowpart = __fadd_rn(rowpart, __fadd_rn(__fadd_rn(w0, w1), __fadd_rn(w2, w3)));
            costw = fmaf(w0, sqrta(fmaxf(d41.x, 1e-24f)), costw);
            costw = fmaf(w1, sqrta(fmaxf(d41.y, 1e-24f)), costw);
            costw = fmaf(w2, sqrta(fmaxf(d41.z, 1e-24f)), costw);
            costw = fmaf(w3, sqrta(fmaxf(d41.w, 1e-24f)), costw);
        }
        if (__any_sync(0xffffffffu, rowpart != 0.0f)) {
#pragma unroll
            for (int o = 16; o; o >>= 1) rowpart += __shfl_xor_sync(0xffffffffu, rowpart, o);
            if (lane == 0) atomicAdd(&s_rowsum[r], rowpart);
        }
    }
    // cost reduction
#pragma unroll
    for (int o = 16; o; o >>= 1) costw += __shfl_xor_sync(0xffffffffu, costw, o);
    if (lane == 0) s_cost[warp] = costw;
    __syncthreads();
    if (threadIdx.x < 8) {
        size_t row = (size_t)(b * NN + row0 + threadIdx.x);
        g_remainL[row] = fmaxf(__fadd_rn(g_remainL[row], -s_rowsum[threadIdx.x]), 0.0f);
    }
    if (threadIdx.x == 0) {
        float cc = 0.0f;
#pragma unroll
        for (int w = 0; w < 8; ++w) cc += s_cost[w];
        if (cc != 0.0f) atomicAdd(&g_cost[b], cc);
    }
    float* colB = g_colB[j3] + b * MM;
    if (col0.x != 0.0f) atomicAdd(&colB[c4 + 0], col0.x);
    if (col0.y != 0.0f) atomicAdd(&colB[c4 + 1], col0.y);
    if (col0.z != 0.0f) atomicAdd(&colB[c4 + 2], col0.z);
    if (col0.w != 0.0f) atomicAdd(&colB[c4 + 3], col0.w);
    if (col1.x != 0.0f) atomicAdd(&colB[c4 + 1024], col1.x);
    if (col1.y != 0.0f) atomicAdd(&colB[c4 + 1025], col1.y);
    if (col1.z != 0.0f) atomicAdd(&colB[c4 + 1026], col1.z);
    if (col1.w != 0.0f) atomicAdd(&colB[c4 + 1027], col1.w);
}

// ---------------------------------------------------------- output
__global__ void k_out(float* out) {
    out[0] = (g_cost[0] + g_cost[1] + g_cost[2] + g_cost[3]) * (1.0f / (BB * NN));
}

// ---------------------------------------------------------------- host
extern "C" void kernel_launch(void* const* d_in, const int* in_sizes, int n_in,
                              void* d_out, int out_size) {
    const float* tm = (const float*)d_in[0];
    const float* sr = (const float*)d_in[1];

    // levels: -4^7 .. -4^-1, then 0; pre-scaled by log2(e)
    const double L2E = 1.4426950408889634;
    float kl2[10];
    double lv = -16384.0;
    for (int j = 0; j < 8; ++j) { kl2[j] = (float)(lv * L2E); lv *= 0.25; }
    kl2[8] = (float)(-0.25 * L2E);
    kl2[9] = 0.0f;

    dim3 gM(256, BB);    // 8 rows per block -> 1024 blocks
    k_d2<<<dim3(256, BB), 256>>>(tm, sr);
    for (int j = 0; j < 10; ++j) {
        int j2 = j & 1, j3 = j % 3, j3p = (j + 2) % 3;
        kA<<<gM, 256>>>(kl2[j], j2, j3, j3p);
        kB<<<gM, 256>>>(kl2[j], j2, j3, j3p);
    }
    k_out<<<1, 1>>>((float*)d_out);
}

// round 16
// speedup vs baseline: 1.1203x; 1.1203x over previous
#include <cuda_runtime.h>
#include <math.h>

#define BB 4
#define NN 2048
#define MM 2048

// ---- persistent scratch (device globals; no allocation allowed) ----
__device__ __align__(16) float g_d2[BB * NN * MM];   // 64 MB squared distances (L2-resident)
__device__ float g_cmin[BB * NN * 16];               // per-row 128-col chunk minima
__device__ float g_remainL[BB * NN];
__device__ __align__(16) float g_R[2][BB * MM];      // remainR double buffer
__device__ float g_ratioL[BB * NN];
__device__ __align__(16) float g_colA[2][BB * MM];   // colsum w0*ratioL (double buffer)
__device__ __align__(16) float g_colB[3][BB * MM];   // colsum w (triple buffer, rotation)
__device__ float g_cost[BB];

__device__ __forceinline__ float ex2a(float x) {
    float y; asm("ex2.approx.f32 %0, %1;" : "=f"(y) : "f"(x)); return y;
}
__device__ __forceinline__ float sqrta(float x) {
    float y; asm("sqrt.approx.f32 %0, %1;" : "=f"(y) : "f"(x)); return y;
}

// ---- d2 (literal fp32 rounding) + chunk minima + state init
__global__ void k_d2(const float* __restrict__ tm, const float* __restrict__ sr) {
    __shared__ alignas(16) float sx[MM];
    __shared__ alignas(16) float sy[MM];
    __shared__ alignas(16) float sz[MM];
    int b = blockIdx.y;
    const float* sb = sr + (size_t)b * MM * 3;
    for (int i = threadIdx.x; i < MM; i += blockDim.x) {
        sx[i] = sb[3 * i]; sy[i] = sb[3 * i + 1]; sz[i] = sb[3 * i + 2];
    }
    if (blockIdx.x == 0) {       // one block per batch initializes state
        int bo = b * MM;
        for (int i = threadIdx.x; i < MM; i += blockDim.x) {
            g_remainL[b * NN + i] = 1.0f;   // multiL = 1 (N == M)
            g_R[0][bo + i] = 1.0f;
            g_R[1][bo + i] = 1.0f;
            g_colA[0][bo + i] = 0.0f;
            g_colA[1][bo + i] = 0.0f;
            g_colB[0][bo + i] = 0.0f;
            g_colB[1][bo + i] = 0.0f;
            g_colB[2][bo + i] = 0.0f;
        }
        if (threadIdx.x == 0) g_cost[b] = 0.0f;
    }
    __syncthreads();
    int warp = threadIdx.x >> 5, lane = threadIdx.x & 31;
    int n = blockIdx.x * 8 + warp;
    size_t row = (size_t)(b * NN + n);
    const float* tp = tm + row * 3;
    float tx = tp[0], ty = tp[1], tz = tp[2];
    float* drow = g_d2 + row * MM;
#pragma unroll 2
    for (int it = 0; it < 16; ++it) {
        int m = it * 128 + lane * 4;
        float4 X = *(const float4*)(sx + m);
        float4 Y = *(const float4*)(sy + m);
        float4 Z = *(const float4*)(sz + m);
        float4 o;
        { float dx = __fadd_rn(tx, -X.x), dy = __fadd_rn(ty, -Y.x), dz = __fadd_rn(tz, -Z.x);
          o.x = __fadd_rn(__fadd_rn(__fmul_rn(dx, dx), __fmul_rn(dy, dy)), __fmul_rn(dz, dz)); }
        { float dx = __fadd_rn(tx, -X.y), dy = __fadd_rn(ty, -Y.y), dz = __fadd_rn(tz, -Z.y);
          o.y = __fadd_rn(__fadd_rn(__fmul_rn(dx, dx), __fmul_rn(dy, dy)), __fmul_rn(dz, dz)); }
        { float dx = __fadd_rn(tx, -X.z), dy = __fadd_rn(ty, -Y.z), dz = __fadd_rn(tz, -Z.z);
          o.z = __fadd_rn(__fadd_rn(__fmul_rn(dx, dx), __fmul_rn(dy, dy)), __fmul_rn(dz, dz)); }
        { float dx = __fadd_rn(tx, -X.w), dy = __fadd_rn(ty, -Y.w), dz = __fadd_rn(tz, -Z.w);
          o.w = __fadd_rn(__fadd_rn(__fmul_rn(dx, dx), __fmul_rn(dy, dy)), __fmul_rn(dz, dz)); }
        *(float4*)(drow + m) = o;
        float mn = fminf(fminf(o.x, o.y), fminf(o.z, o.w));
#pragma unroll
        for (int s = 16; s; s >>= 1) mn = fminf(mn, __shfl_xor_sync(0xffffffffu, mn, s));
        if (lane == 0) g_cmin[row * 16 + it] = mn;
    }
}

// --------------------------------------------------------------- kA
// Level j: j2=j%2, j3=j%3, j3p=(j+2)%3.
// Phase 1: rm_eff = max(R[j2]-colB[j3p],0) on the fly (active chunks only);
// suml -> ratioL. Phase 2: colA[j2] atomics.
// Maintenance (block x==0 ONLY -> single writer, no duplicate-store
// contention): zero colB[j3] for kB(j)'s accumulation (readers of that
// buffer finished at level j-2 by rotation; kB(j) runs after kA(j)).
__global__ void __launch_bounds__(256, 5) kA(float kl2, int j2, int j3, int j3p) {
    __shared__ float s_rl[8];
    __shared__ float s_cm[8 * 16];
    int b = blockIdx.y;
    int row0 = blockIdx.x * 8;
    if (threadIdx.x < 128)
        s_cm[threadIdx.x] = g_cmin[(size_t)(b * NN + row0) * 16 + threadIdx.x];
    __syncthreads();
    int warp = threadIdx.x >> 5, lane = threadIdx.x & 31;
    // ---- phase 1: one row per warp
    {
        size_t row = (size_t)(b * NN + row0 + warp);
        const float* drow = g_d2 + row * MM;
        const float* rmg = g_R[j2] + b * MM;
        const float* cbg = g_colB[j3p] + b * MM;
        float suml = 0.0f;
#pragma unroll 2
        for (int it = 0; it < 16; ++it) {
            if (__fmul_rn(kl2, s_cm[warp * 16 + it]) > -126.0f) {
                int m = it * 128 + lane * 4;
                float4 d4 = *(const float4*)(drow + m);
                float4 rm = __ldg((const float4*)(rmg + m));
                float4 cb = __ldg((const float4*)(cbg + m));
                rm.x = fmaxf(__fadd_rn(rm.x, -cb.x), 0.0f);
                rm.y = fmaxf(__fadd_rn(rm.y, -cb.y), 0.0f);
                rm.z = fmaxf(__fadd_rn(rm.z, -cb.z), 0.0f);
                rm.w = fmaxf(__fadd_rn(rm.w, -cb.w), 0.0f);
                suml = fmaf(ex2a(__fmul_rn(kl2, d4.x)), rm.x, suml);
                suml = fmaf(ex2a(__fmul_rn(kl2, d4.y)), rm.y, suml);
                suml = fmaf(ex2a(__fmul_rn(kl2, d4.z)), rm.z, suml);
                suml = fmaf(ex2a(__fmul_rn(kl2, d4.w)), rm.w, suml);
            }
        }
#pragma unroll
        for (int o = 16; o; o >>= 1) suml += __shfl_xor_sync(0xffffffffu, suml, o);
        if (lane == 0) {
            float rl = g_remainL[row] / (suml + 1e-9f);
            s_rl[warp] = rl;
            g_ratioL[row] = rl;
        }
    }
    __syncthreads();
    // ---- phase 2: thread owns cols 4*tid + 1024*k (k = 0,1)
    int c4 = threadIdx.x * 4;
    float4 acc0 = make_float4(0, 0, 0, 0), acc1 = make_float4(0, 0, 0, 0);
    int ch0 = warp, ch1 = warp + 8;
#pragma unroll 2
    for (int r = 0; r < 8; ++r) {
        const float* drow = g_d2 + ((size_t)(b * NN + row0 + r)) * MM;
        float rl = s_rl[r];
        bool a0 = __fmul_rn(kl2, s_cm[r * 16 + ch0]) > -126.0f;
        bool a1 = __fmul_rn(kl2, s_cm[r * 16 + ch1]) > -126.0f;
        float4 d40, d41;
        if (a0) d40 = *(const float4*)(drow + c4);          // loads first (MLP)
        if (a1) d41 = *(const float4*)(drow + c4 + 1024);
        if (a0) {
            acc0.x = fmaf(ex2a(__fmul_rn(kl2, d40.x)), rl, acc0.x);
            acc0.y = fmaf(ex2a(__fmul_rn(kl2, d40.y)), rl, acc0.y);
            acc0.z = fmaf(ex2a(__fmul_rn(kl2, d40.z)), rl, acc0.z);
            acc0.w = fmaf(ex2a(__fmul_rn(kl2, d40.w)), rl, acc0.w);
        }
        if (a1) {
            acc1.x = fmaf(ex2a(__fmul_rn(kl2, d41.x)), rl, acc1.x);
            acc1.y = fmaf(ex2a(__fmul_rn(kl2, d41.y)), rl, acc1.y);
            acc1.z = fmaf(ex2a(__fmul_rn(kl2, d41.z)), rl, acc1.z);
            acc1.w = fmaf(ex2a(__fmul_rn(kl2, d41.w)), rl, acc1.w);
        }
    }
    float* colA = g_colA[j2] + b * MM;
    if (acc0.x != 0.0f) atomicAdd(&colA[c4 + 0], acc0.x);
    if (acc0.y != 0.0f) atomicAdd(&colA[c4 + 1], acc0.y);
    if (acc0.z != 0.0f) atomicAdd(&colA[c4 + 2], acc0.z);
    if (acc0.w != 0.0f) atomicAdd(&colA[c4 + 3], acc0.w);
    if (acc1.x != 0.0f) atomicAdd(&colA[c4 + 1024], acc1.x);
    if (acc1.y != 0.0f) atomicAdd(&colA[c4 + 1025], acc1.y);
    if (acc1.z != 0.0f) atomicAdd(&colA[c4 + 1026], acc1.z);
    if (acc1.w != 0.0f) atomicAdd(&colA[c4 + 1027], acc1.w);
    // single-writer maintenance: zero colB[j3] for kB(j)
    if (blockIdx.x == 0) {
        float* cbz = g_colB[j3] + b * MM;
        float4 z4 = make_float4(0.0f, 0.0f, 0.0f, 0.0f);
        *(float4*)(cbz + c4) = z4;
        *(float4*)(cbz + c4 + 1024) = z4;
    }
}

// --------------------------------------------------------------- kB
// Prologue (all blocks, duplicate COMPUTE only): rm_eff = max(R[j2]-colB[j3p],0);
// ratioR = rm_eff/(colA[j2]+1e-9) for this thread's 8 columns.
// Maintenance (block x==0 ONLY): persist R[1-j2] = rm_eff (256 threads cover
// all 2048 columns exactly once); zero colA[1-j2] for kA(j+1).
// Hot loop identical to the 370us champion.
__global__ void __launch_bounds__(256, 5) kB(float kl2, int j2, int j3, int j3p) {
    __shared__ float s_rl[8];
    __shared__ float s_rowsum[8];
    __shared__ float s_cost[8];
    __shared__ float s_cm[8 * 16];
    int b = blockIdx.y;
    int row0 = blockIdx.x * 8;
    if (threadIdx.x < 128)
        s_cm[threadIdx.x] = g_cmin[(size_t)(b * NN + row0) * 16 + threadIdx.x];
    if (threadIdx.x < 8) {
        s_rl[threadIdx.x] = g_ratioL[b * NN + row0 + threadIdx.x];
        s_rowsum[threadIdx.x] = 0.0f;
    }
    __syncthreads();
    int warp = threadIdx.x >> 5, lane = threadIdx.x & 31;
    int c4 = threadIdx.x * 4;
    int ch0 = warp, ch1 = warp + 8;
    // ---- prologue: rm_eff + ratioR for this thread's 8 columns
    const float* Rrd = g_R[j2] + b * MM;
    const float* cbp = g_colB[j3p] + b * MM;
    const float* cag = g_colA[j2] + b * MM;
    float4 rm0 = __ldg((const float4*)(Rrd + c4));
    float4 rm1 = __ldg((const float4*)(Rrd + c4 + 1024));
    float4 cb0 = __ldg((const float4*)(cbp + c4));
    float4 cb1 = __ldg((const float4*)(cbp + c4 + 1024));
    float4 ca0 = __ldg((const float4*)(cag + c4));
    float4 ca1 = __ldg((const float4*)(cag + c4 + 1024));
    float4 rme0, rme1;
    rme0.x = fmaxf(__fadd_rn(rm0.x, -cb0.x), 0.0f);
    rme0.y = fmaxf(__fadd_rn(rm0.y, -cb0.y), 0.0f);
    rme0.z = fmaxf(__fadd_rn(rm0.z, -cb0.z), 0.0f);
    rme0.w = fmaxf(__fadd_rn(rm0.w, -cb0.w), 0.0f);
    rme1.x = fmaxf(__fadd_rn(rm1.x, -cb1.x), 0.0f);
    rme1.y = fmaxf(__fadd_rn(rm1.y, -cb1.y), 0.0f);
    rme1.z = fmaxf(__fadd_rn(rm1.z, -cb1.z), 0.0f);
    rme1.w = fmaxf(__fadd_rn(rm1.w, -cb1.w), 0.0f);
    float4 rr0, rr1;
    rr0.x = rme0.x / (ca0.x + 1e-9f); rr0.y = rme0.y / (ca0.y + 1e-9f);
    rr0.z = rme0.z / (ca0.z + 1e-9f); rr0.w = rme0.w / (ca0.w + 1e-9f);
    rr1.x = rme1.x / (ca1.x + 1e-9f); rr1.y = rme1.y / (ca1.y + 1e-9f);
    rr1.z = rme1.z / (ca1.z + 1e-9f); rr1.w = rme1.w / (ca1.w + 1e-9f);
    if (blockIdx.x == 0) {   // single-writer maintenance
        float* Rwr = g_R[1 - j2] + b * MM;
        float* caz = g_colA[1 - j2] + b * MM;
        *(float4*)(Rwr + c4) = rme0;
        *(float4*)(Rwr + c4 + 1024) = rme1;
        float4 z4 = make_float4(0.0f, 0.0f, 0.0f, 0.0f);
        *(float4*)(caz + c4) = z4;
        *(float4*)(caz + c4 + 1024) = z4;
    }
    float4 col0 = make_float4(0, 0, 0, 0), col1 = make_float4(0, 0, 0, 0);
    float costw = 0.0f;
#pragma unroll 2
    for (int r = 0; r < 8; ++r) {
        float rl = s_rl[r];
        const float* drow = g_d2 + ((size_t)(b * NN + row0 + r)) * MM;
        bool a0 = (rl != 0.0f) && (__fmul_rn(kl2, s_cm[r * 16 + ch0]) > -126.0f);
        bool a1 = (rl != 0.0f) && (__fmul_rn(kl2, s_cm[r * 16 + ch1]) > -126.0f);
        float4 d40, d41;
        if (a0) d40 = *(const float4*)(drow + c4);
        if (a1) d41 = *(const float4*)(drow + c4 + 1024);
        float rowpart = 0.0f;
        if (a0) {
            float w0 = __fmul_rn(__fmul_rn(ex2a(__fmul_rn(kl2, d40.x)), rl), rr0.x);
            float w1 = __fmul_rn(__fmul_rn(ex2a(__fmul_rn(kl2, d40.y)), rl), rr0.y);
            float w2 = __fmul_rn(__fmul_rn(ex2a(__fmul_rn(kl2, d40.z)), rl), rr0.z);
            float w3 = __fmul_rn(__fmul_rn(ex2a(__fmul_rn(kl2, d40.w)), rl), rr0.w);
            col0.x = __fadd_rn(col0.x, w0); col0.y = __fadd_rn(col0.y, w1);
            col0.z = __fadd_rn(col0.z, w2); col0.w = __fadd_rn(col0.w, w3);
            rowpart = __fadd_rn(rowpart, __fadd_rn(__fadd_rn(w0, w1), __fadd_rn(w2, w3)));
            costw = fmaf(w0, sqrta(fmaxf(d40.x, 1e-24f)), costw);
            costw = fmaf(w1, sqrta(fmaxf(d40.y, 1e-24f)), costw);
            costw = fmaf(w2, sqrta(fmaxf(d40.z, 1e-24f)), costw);
            costw = fmaf(w3, sqrta(fmaxf(d40.w, 1e-24f)), costw);
        }
        if (a1) {
            float w0 = __fmul_rn(__fmul_rn(ex2a(__fmul_rn(kl2, d41.x)), rl), rr1.x);
            float w1 = __fmul_rn(__fmul_rn(ex2a(__fmul_rn(kl2, d41.y)), rl), rr1.y);
            float w2 = __fmul_rn(__fmul_rn(ex2a(__fmul_rn(kl2, d41.z)), rl), rr1.z);
            float w3 = __fmul_rn(__fmul_rn(ex2a(__fmul_rn(kl2, d41.w)), rl), rr1.w);
            col1.x = __fadd_rn(col1.x, w0); col1.y = __fadd_rn(col1.y, w1);
            col1.z = __fadd_rn(col1.z, w2); col1.w = __fadd_rn(col1.w, w3);
            rowpart = __fadd_rn(rowpart, __fadd_rn(__fadd_rn(w0, w1), __fadd_rn(w2, w3)));
            costw = fmaf(w0, sqrta(fmaxf(d41.x, 1e-24f)), costw);
            costw = fmaf(w1, sqrta(fmaxf(d41.y, 1e-24f)), costw);
            costw = fmaf(w2, sqrta(fmaxf(d41.z, 1e-24f)), costw);
            costw = fmaf(w3, sqrta(fmaxf(d41.w, 1e-24f)), costw);
        }
        if (__any_sync(0xffffffffu, rowpart != 0.0f)) {
#pragma unroll
            for (int o = 16; o; o >>= 1) rowpart += __shfl_xor_sync(0xffffffffu, rowpart, o);
            if (lane == 0) atomicAdd(&s_rowsum[r], rowpart);
        }
    }
    // cost reduction
#pragma unroll
    for (int o = 16; o; o >>= 1) costw += __shfl_xor_sync(0xffffffffu, costw, o);
    if (lane == 0) s_cost[warp] = costw;
    __syncthreads();
    if (threadIdx.x < 8) {
        size_t row = (size_t)(b * NN + row0 + threadIdx.x);
        g_remainL[row] = fmaxf(__fadd_rn(g_remainL[row], -s_rowsum[threadIdx.x]), 0.0f);
    }
    if (threadIdx.x == 0) {
        float cc = 0.0f;
#pragma unroll
        for (int w = 0; w < 8; ++w) cc += s_cost[w];
        if (cc != 0.0f) atomicAdd(&g_cost[b], cc);
    }
    float* colB = g_colB[j3] + b * MM;
    if (col0.x != 0.0f) atomicAdd(&colB[c4 + 0], col0.x);
    if (col0.y != 0.0f) atomicAdd(&colB[c4 + 1], col0.y);
    if (col0.z != 0.0f) atomicAdd(&colB[c4 + 2], col0.z);
    if (col0.w != 0.0f) atomicAdd(&colB[c4 + 3], col0.w);
    if (col1.x != 0.0f) atomicAdd(&colB[c4 + 1024], col1.x);
    if (col1.y != 0.0f) atomicAdd(&colB[c4 + 1025], col1.y);
    if (col1.z != 0.0f) atomicAdd(&colB[c4 + 1026], col1.z);
    if (col1.w != 0.0f) atomicAdd(&colB[c4 + 1027], col1.w);
}

// ---------------------------------------------------------- output
__global__ void k_out(float* out) {
    out[0] = (g_cost[0] + g_cost[1] + g_cost[2] + g_cost[3]) * (1.0f / (BB * NN));
}

// ---------------------------------------------------------------- host
extern "C" void kernel_launch(void* const* d_in, const int* in_sizes, int n_in,
                              void* d_out, int out_size) {
    const float* tm = (const float*)d_in[0];
    const float* sr = (const float*)d_in[1];

    // levels: -4^7 .. -4^-1, then 0; pre-scaled by log2(e)
    const double L2E = 1.4426950408889634;
    float kl2[10];
    double lv = -16384.0;
    for (int j = 0; j < 8; ++j) { kl2[j] = (float)(lv * L2E); lv *= 0.25; }
    kl2[8] = (float)(-0.25 * L2E);
    kl2[9] = 0.0f;

    dim3 gM(256, BB);    // 8 rows per block -> 1024 blocks
    k_d2<<<dim3(256, BB), 256>>>(tm, sr);
    for (int j = 0; j < 10; ++j) {
        int j2 = j & 1, j3 = j % 3, j3p = (j + 2) % 3;
        kA<<<gM, 256>>>(kl2[j], j2, j3, j3p);
        kB<<<gM, 256>>>(kl2[j], j2, j3, j3p);
    }
    k_out<<<1, 1>>>((float*)d_out);
}

// round 17
// speedup vs baseline: 1.2978x; 1.1585x over previous
#include <cuda_runtime.h>
#include <cooperative_groups.h>
#include <math.h>

namespace cg = cooperative_groups;

#define BB 4
#define NN 2048
#define MM 2048
#define RPB 16        // rows per block
#define BLKX (NN / RPB)   // 128 blocks per batch -> 512 total

// ---- persistent scratch (device globals; no allocation allowed) ----
__device__ __align__(16) float g_d2[BB * NN * MM];   // 64 MB (L2-resident)
__device__ float g_remainL[BB * NN];
__device__ __align__(16) float g_R[2][BB * MM];      // remainR double buffer
__device__ __align__(16) float g_colA[2][BB * MM];   // colsum w0*ratioL (rotation)
__device__ __align__(16) float g_colB[3][BB * MM];   // colsum w (rotation)
__device__ float g_cost[BB];

__device__ __forceinline__ float ex2a(float x) {
    float y; asm("ex2.approx.f32 %0, %1;" : "=f"(y) : "f"(x)); return y;
}
__device__ __forceinline__ float sqrta(float x) {
    float y; asm("sqrt.approx.f32 %0, %1;" : "=f"(y) : "f"(x)); return y;
}

__global__ void __launch_bounds__(256, 4) kMain(const float* __restrict__ tm,
                                                const float* __restrict__ sr,
                                                float* __restrict__ out) {
    cg::grid_group grid = cg::this_grid();
    __shared__ alignas(16) float sx[MM];
    __shared__ alignas(16) float sy[MM];
    __shared__ alignas(16) float sz[MM];
    __shared__ float s_cm[RPB * 16];     // per-row chunk minima (this block's rows)
    __shared__ float s_rl[RPB];
    __shared__ float s_rowsum[RPB];
    __shared__ float s_cost[8];
    int b = blockIdx.y;
    int row0 = blockIdx.x * RPB;
    int tid = threadIdx.x, warp = tid >> 5, lane = tid & 31;
    int c4 = tid * 4;

    // ================= phase D: source load + state init + d2 + cmin ==========
    const float* sb = sr + (size_t)b * MM * 3;
    for (int i = tid; i < MM; i += 256) {
        sx[i] = sb[3 * i]; sy[i] = sb[3 * i + 1]; sz[i] = sb[3 * i + 2];
    }
    if (blockIdx.x == 0) {
        int bo = b * MM;
        for (int i = tid; i < MM; i += 256) {
            g_remainL[b * NN + i] = 1.0f;   // multiL = 1 (N == M)
            g_R[0][bo + i] = 1.0f; g_R[1][bo + i] = 1.0f;
            g_colA[0][bo + i] = 0.0f; g_colA[1][bo + i] = 0.0f;
            g_colB[0][bo + i] = 0.0f; g_colB[1][bo + i] = 0.0f; g_colB[2][bo + i] = 0.0f;
        }
        if (tid == 0) g_cost[b] = 0.0f;
    }
    __syncthreads();
#pragma unroll 1
    for (int r2 = 0; r2 < 2; ++r2) {
        int rloc = warp * 2 + r2;
        size_t row = (size_t)(b * NN + row0 + rloc);
        const float* tp = tm + row * 3;
        float tx = tp[0], ty = tp[1], tz = tp[2];
        float* drow = g_d2 + row * MM;
#pragma unroll 2
        for (int it = 0; it < 16; ++it) {
            int m = it * 128 + lane * 4;
            float4 X = *(const float4*)(sx + m);
            float4 Y = *(const float4*)(sy + m);
            float4 Z = *(const float4*)(sz + m);
            float4 o;
            { float dx = __fadd_rn(tx, -X.x), dy = __fadd_rn(ty, -Y.x), dz = __fadd_rn(tz, -Z.x);
              o.x = __fadd_rn(__fadd_rn(__fmul_rn(dx, dx), __fmul_rn(dy, dy)), __fmul_rn(dz, dz)); }
            { float dx = __fadd_rn(tx, -X.y), dy = __fadd_rn(ty, -Y.y), dz = __fadd_rn(tz, -Z.y);
              o.y = __fadd_rn(__fadd_rn(__fmul_rn(dx, dx), __fmul_rn(dy, dy)), __fmul_rn(dz, dz)); }
            { float dx = __fadd_rn(tx, -X.z), dy = __fadd_rn(ty, -Y.z), dz = __fadd_rn(tz, -Z.z);
              o.z = __fadd_rn(__fadd_rn(__fmul_rn(dx, dx), __fmul_rn(dy, dy)), __fmul_rn(dz, dz)); }
            { float dx = __fadd_rn(tx, -X.w), dy = __fadd_rn(ty, -Y.w), dz = __fadd_rn(tz, -Z.w);
              o.w = __fadd_rn(__fadd_rn(__fmul_rn(dx, dx), __fmul_rn(dy, dy)), __fmul_rn(dz, dz)); }
            *(float4*)(drow + m) = o;
            float mn = fminf(fminf(o.x, o.y), fminf(o.z, o.w));
#pragma unroll
            for (int s = 16; s; s >>= 1) mn = fminf(mn, __shfl_xor_sync(0xffffffffu, mn, s));
            if (lane == 0) s_cm[rloc * 16 + it] = mn;
        }
    }
    __syncthreads();
    grid.sync();

    // levels pre-scaled by log2(e), same host-double derivation as before
    const double L2E = 1.4426950408889634;
    float kl2[10];
    double lv = -16384.0;
#pragma unroll
    for (int j = 0; j < 8; ++j) { kl2[j] = (float)(lv * L2E); lv *= 0.25; }
    kl2[8] = (float)(-0.25 * L2E);
    kl2[9] = 0.0f;

#pragma unroll 1
    for (int j = 0; j < 10; ++j) {
        float kl = kl2[j];
        int j2 = j & 1, j3 = j % 3, j3p = (j + 2) % 3;

        // ===== phase A1: suml -> ratioL (2 rows per warp), rm_eff on the fly
        {
            const float* rmg = g_R[j2] + b * MM;
            const float* cbg = g_colB[j3p] + b * MM;
#pragma unroll 1
            for (int r2 = 0; r2 < 2; ++r2) {
                int rloc = warp * 2 + r2;
                size_t row = (size_t)(b * NN + row0 + rloc);
                const float* drow = g_d2 + row * MM;
                float suml = 0.0f;
#pragma unroll 2
                for (int it = 0; it < 16; ++it) {
                    if (__fmul_rn(kl, s_cm[rloc * 16 + it]) > -126.0f) {
                        int m = it * 128 + lane * 4;
                        float4 d4 = *(const float4*)(drow + m);
                        float4 rm = __ldg((const float4*)(rmg + m));
                        float4 cb = __ldg((const float4*)(cbg + m));
                        rm.x = fmaxf(__fadd_rn(rm.x, -cb.x), 0.0f);
                        rm.y = fmaxf(__fadd_rn(rm.y, -cb.y), 0.0f);
                        rm.z = fmaxf(__fadd_rn(rm.z, -cb.z), 0.0f);
                        rm.w = fmaxf(__fadd_rn(rm.w, -cb.w), 0.0f);
                        suml = fmaf(ex2a(__fmul_rn(kl, d4.x)), rm.x, suml);
                        suml = fmaf(ex2a(__fmul_rn(kl, d4.y)), rm.y, suml);
                        suml = fmaf(ex2a(__fmul_rn(kl, d4.z)), rm.z, suml);
                        suml = fmaf(ex2a(__fmul_rn(kl, d4.w)), rm.w, suml);
                    }
                }
#pragma unroll
                for (int o = 16; o; o >>= 1) suml += __shfl_xor_sync(0xffffffffu, suml, o);
                if (lane == 0)
                    s_rl[rloc] = g_remainL[row] / (suml + 1e-9f);
            }
        }
        __syncthreads();
        // ===== phase A2: colA[j2] atomics, column ownership over 16 rows
        {
            float4 acc0 = make_float4(0, 0, 0, 0), acc1 = make_float4(0, 0, 0, 0);
            int ch0 = warp, ch1 = warp + 8;
#pragma unroll 2
            for (int r = 0; r < RPB; ++r) {
                const float* drow = g_d2 + ((size_t)(b * NN + row0 + r)) * MM;
                float rl = s_rl[r];
                bool a0 = __fmul_rn(kl, s_cm[r * 16 + ch0]) > -126.0f;
                bool a1 = __fmul_rn(kl, s_cm[r * 16 + ch1]) > -126.0f;
                float4 d40, d41;
                if (a0) d40 = *(const float4*)(drow + c4);
                if (a1) d41 = *(const float4*)(drow + c4 + 1024);
                if (a0) {
                    acc0.x = fmaf(ex2a(__fmul_rn(kl, d40.x)), rl, acc0.x);
                    acc0.y = fmaf(ex2a(__fmul_rn(kl, d40.y)), rl, acc0.y);
                    acc0.z = fmaf(ex2a(__fmul_rn(kl, d40.z)), rl, acc0.z);
                    acc0.w = fmaf(ex2a(__fmul_rn(kl, d40.w)), rl, acc0.w);
                }
                if (a1) {
                    acc1.x = fmaf(ex2a(__fmul_rn(kl, d41.x)), rl, acc1.x);
                    acc1.y = fmaf(ex2a(__fmul_rn(kl, d41.y)), rl, acc1.y);
                    acc1.z = fmaf(ex2a(__fmul_rn(kl, d41.z)), rl, acc1.z);
                    acc1.w = fmaf(ex2a(__fmul_rn(kl, d41.w)), rl, acc1.w);
                }
            }
            float* colA = g_colA[j2] + b * MM;
            if (acc0.x != 0.0f) atomicAdd(&colA[c4 + 0], acc0.x);
            if (acc0.y != 0.0f) atomicAdd(&colA[c4 + 1], acc0.y);
            if (acc0.z != 0.0f) atomicAdd(&colA[c4 + 2], acc0.z);
            if (acc0.w != 0.0f) atomicAdd(&colA[c4 + 3], acc0.w);
            if (acc1.x != 0.0f) atomicAdd(&colA[c4 + 1024], acc1.x);
            if (acc1.y != 0.0f) atomicAdd(&colA[c4 + 1025], acc1.y);
            if (acc1.z != 0.0f) atomicAdd(&colA[c4 + 1026], acc1.z);
            if (acc1.w != 0.0f) atomicAdd(&colA[c4 + 1027], acc1.w);
        }
        // single writer: zero colB[j3] for this level's kB accumulation
        if (blockIdx.x == 1) {
            float* cbz = g_colB[j3] + b * MM;
            float4 z4 = make_float4(0.0f, 0.0f, 0.0f, 0.0f);
            *(float4*)(cbz + c4) = z4;
            *(float4*)(cbz + c4 + 1024) = z4;
        }
        grid.sync();   // colA complete; colB[j3] zeroed

        // ===== phase B prologue: rm_eff + inline ratioR for own 8 columns
        const float* Rrd = g_R[j2] + b * MM;
        const float* cbp = g_colB[j3p] + b * MM;
        const float* cag = g_colA[j2] + b * MM;
        float4 rm0 = __ldg((const float4*)(Rrd + c4));
        float4 rm1 = __ldg((const float4*)(Rrd + c4 + 1024));
        float4 cb0 = __ldg((const float4*)(cbp + c4));
        float4 cb1 = __ldg((const float4*)(cbp + c4 + 1024));
        float4 ca0 = __ldg((const float4*)(cag + c4));
        float4 ca1 = __ldg((const float4*)(cag + c4 + 1024));
        float4 rme0, rme1;
        rme0.x = fmaxf(__fadd_rn(rm0.x, -cb0.x), 0.0f);
        rme0.y = fmaxf(__fadd_rn(rm0.y, -cb0.y), 0.0f);
        rme0.z = fmaxf(__fadd_rn(rm0.z, -cb0.z), 0.0f);
        rme0.w = fmaxf(__fadd_rn(rm0.w, -cb0.w), 0.0f);
        rme1.x = fmaxf(__fadd_rn(rm1.x, -cb1.x), 0.0f);
        rme1.y = fmaxf(__fadd_rn(rm1.y, -cb1.y), 0.0f);
        rme1.z = fmaxf(__fadd_rn(rm1.z, -cb1.z), 0.0f);
        rme1.w = fmaxf(__fadd_rn(rm1.w, -cb1.w), 0.0f);
        float4 rr0, rr1;
        rr0.x = rme0.x / (ca0.x + 1e-9f); rr0.y = rme0.y / (ca0.y + 1e-9f);
        rr0.z = rme0.z / (ca0.z + 1e-9f); rr0.w = rme0.w / (ca0.w + 1e-9f);
        rr1.x = rme1.x / (ca1.x + 1e-9f); rr1.y = rme1.y / (ca1.y + 1e-9f);
        rr1.z = rme1.z / (ca1.z + 1e-9f); rr1.w = rme1.w / (ca1.w + 1e-9f);
        if (blockIdx.x == 0) {   // single-writer maintenance for level j+1
            float* Rwr = g_R[1 - j2] + b * MM;
            float* caz = g_colA[1 - j2] + b * MM;
            *(float4*)(Rwr + c4) = rme0;
            *(float4*)(Rwr + c4 + 1024) = rme1;
            float4 z4 = make_float4(0.0f, 0.0f, 0.0f, 0.0f);
            *(float4*)(caz + c4) = z4;
            *(float4*)(caz + c4 + 1024) = z4;
        }
        if (tid < RPB) s_rowsum[tid] = 0.0f;
        __syncthreads();
        // ===== phase B hot loop
        {
            int ch0 = warp, ch1 = warp + 8;
            float4 col0 = make_float4(0, 0, 0, 0), col1 = make_float4(0, 0, 0, 0);
            float costw = 0.0f;
#pragma unroll 2
            for (int r = 0; r < RPB; ++r) {
                float rl = s_rl[r];
                const float* drow = g_d2 + ((size_t)(b * NN + row0 + r)) * MM;
                bool a0 = (rl != 0.0f) && (__fmul_rn(kl, s_cm[r * 16 + ch0]) > -126.0f);
                bool a1 = (rl != 0.0f) && (__fmul_rn(kl, s_cm[r * 16 + ch1]) > -126.0f);
                float4 d40, d41;
                if (a0) d40 = *(const float4*)(drow + c4);
                if (a1) d41 = *(const float4*)(drow + c4 + 1024);
                float rowpart = 0.0f;
                if (a0) {
                    float w0 = __fmul_rn(__fmul_rn(ex2a(__fmul_rn(kl, d40.x)), rl), rr0.x);
                    float w1 = __fmul_rn(__fmul_rn(ex2a(__fmul_rn(kl, d40.y)), rl), rr0.y);
                    float w2 = __fmul_rn(__fmul_rn(ex2a(__fmul_rn(kl, d40.z)), rl), rr0.z);
                    float w3 = __fmul_rn(__fmul_rn(ex2a(__fmul_rn(kl, d40.w)), rl), rr0.w);
                    col0.x = __fadd_rn(col0.x, w0); col0.y = __fadd_rn(col0.y, w1);
                    col0.z = __fadd_rn(col0.z, w2); col0.w = __fadd_rn(col0.w, w3);
                    rowpart = __fadd_rn(rowpart, __fadd_rn(__fadd_rn(w0, w1), __fadd_rn(w2, w3)));
                    costw = fmaf(w0, sqrta(fmaxf(d40.x, 1e-24f)), costw);
                    costw = fmaf(w1, sqrta(fmaxf(d40.y, 1e-24f)), costw);
                    costw = fmaf(w2, sqrta(fmaxf(d40.z, 1e-24f)), costw);
                    costw = fmaf(w3, sqrta(fmaxf(d40.w, 1e-24f)), costw);
                }
                if (a1) {
                    float w0 = __fmul_rn(__fmul_rn(ex2a(__fmul_rn(kl, d41.x)), rl), rr1.x);
                    float w1 = __fmul_rn(__fmul_rn(ex2a(__fmul_rn(kl, d41.y)), rl), rr1.y);
                    float w2 = __fmul_rn(__fmul_rn(ex2a(__fmul_rn(kl, d41.z)), rl), rr1.z);
                    float w3 = __fmul_rn(__fmul_rn(ex2a(__fmul_rn(kl, d41.w)), rl), rr1.w);
                    col1.x = __fadd_rn(col1.x, w0); col1.y = __fadd_rn(col1.y, w1);
                    col1.z = __fadd_rn(col1.z, w2); col1.w = __fadd_rn(col1.w, w3);
                    rowpart = __fadd_rn(rowpart, __fadd_rn(__fadd_rn(w0, w1), __fadd_rn(w2, w3)));
                    costw = fmaf(w0, sqrta(fmaxf(d41.x, 1e-24f)), costw);
                    costw = fmaf(w1, sqrta(fmaxf(d41.y, 1e-24f)), costw);
                    costw = fmaf(w2, sqrta(fmaxf(d41.z, 1e-24f)), costw);
                    costw = fmaf(w3, sqrta(fmaxf(d41.w, 1e-24f)), costw);
                }
                if (__any_sync(0xffffffffu, rowpart != 0.0f)) {
#pragma unroll
                    for (int o = 16; o; o >>= 1)
                        rowpart += __shfl_xor_sync(0xffffffffu, rowpart, o);
                    if (lane == 0) atomicAdd(&s_rowsum[r], rowpart);
                }
            }
#pragma unroll
            for (int o = 16; o; o >>= 1) costw += __shfl_xor_sync(0xffffffffu, costw, o);
            if (lane == 0) s_cost[warp] = costw;
            __syncthreads();
            if (tid < RPB) {
                size_t row = (size_t)(b * NN + row0 + tid);
                g_remainL[row] = fmaxf(__fadd_rn(g_remainL[row], -s_rowsum[tid]), 0.0f);
            }
            if (tid == 0) {
                float cc = 0.0f;
#pragma unroll
                for (int w = 0; w < 8; ++w) cc += s_cost[w];
                if (cc != 0.0f) atomicAdd(&g_cost[b], cc);
            }
            float* colB = g_colB[j3] + b * MM;
            if (col0.x != 0.0f) atomicAdd(&colB[c4 + 0], col0.x);
            if (col0.y != 0.0f) atomicAdd(&colB[c4 + 1], col0.y);
            if (col0.z != 0.0f) atomicAdd(&colB[c4 + 2], col0.z);
            if (col0.w != 0.0f) atomicAdd(&colB[c4 + 3], col0.w);
            if (col1.x != 0.0f) atomicAdd(&colB[c4 + 1024], col1.x);
            if (col1.y != 0.0f) atomicAdd(&colB[c4 + 1025], col1.y);
            if (col1.z != 0.0f) atomicAdd(&colB[c4 + 1026], col1.z);
            if (col1.w != 0.0f) atomicAdd(&colB[c4 + 1027], col1.w);
        }
        grid.sync();   // colB complete; R/colA maintenance visible
    }

    // ---------------- output
    if (blockIdx.x == 0 && blockIdx.y == 0 && tid == 0)
        out[0] = (g_cost[0] + g_cost[1] + g_cost[2] + g_cost[3]) * (1.0f / (BB * NN));
}

// ---------------------------------------------------------------- host
extern "C" void kernel_launch(void* const* d_in, const int* in_sizes, int n_in,
                              void* d_out, int out_size) {
    const float* tm = (const float*)d_in[0];
    const float* sr = (const float*)d_in[1];
    float* outp = (float*)d_out;
    void* args[3] = {(void*)&tm, (void*)&sr, (void*)&outp};
    cudaLaunchCooperativeKernel((const void*)kMain, dim3(BLKX, BB, 1), dim3(256, 1, 1),
                                args, 0, (cudaStream_t)0);
}